// round 1
// baseline (speedup 1.0000x reference)
#include <cuda_runtime.h>
#include <math.h>
#include <cfloat>

// ---------------------------------------------------------------------------
// MIL-NCE head: s = (v @ t^T)/0.1 with N=4096, T=4, D=256 (NT=16384)
// Outputs: [loss, recall1, recall5, recall10, avg_rank] (5 f32 scalars)
//
// Plan:
//  K0 init:    rmax/cmax <- -inf (encoded int)
//  K1 gemm:    S tile -> scratch, per-row/col tile maxes -> atomicMax (exact,
//              deterministic, idempotent across graph replays)
//  K2 colsum:  column-wise sum(exp(x - cmax)) with threshold cut (almost no exp)
//  K3 row:     per-row: ranks of the 4 positives, row sum(exp(x - rmax)),
//              nominator/denominator LSE combine, per-row metrics
//  K4 reduce:  deterministic tree reduction -> 5 means
// ---------------------------------------------------------------------------

namespace {
constexpr int N  = 4096;
constexpr int T  = 4;
constexpr int NT = 16384;
constexpr int D  = 256;
constexpr int BM = 128, BN = 128, BK = 16;
constexpr int RTILES = N / BM;      // 32
constexpr float SCALE = 10.0f;      // 1 / temperature
constexpr float LSE_CUT = 30.0f;    // exp(-30)*16384 ~ 1.5e-9 absolute on the log
}

// scratch (device globals are the sanctioned scratch path; no allocs anywhere)
__device__ float g_S[(size_t)N * NT];       // 256 MB score matrix
__device__ int   g_rmax[N];                 // encoded row maxes
__device__ int   g_cmax[NT];                // encoded col maxes
__device__ float g_cpart[RTILES][NT];       // column partial sumexp per 128-row tile
__device__ float g_rowout[N][5];            // per-row: loss, r1, r5, r10, avg_rank

// order-preserving float<->int encoding (for deterministic atomicMax)
__device__ __forceinline__ int enc_f(float f) {
    int i = __float_as_int(f);
    return i >= 0 ? i : i ^ 0x7fffffff;
}
__device__ __forceinline__ float dec_f(int i) {
    return __int_as_float(i >= 0 ? i : i ^ 0x7fffffff);
}

// ---------------------------------------------------------------------------
__global__ void init_kernel() {
    int idx = blockIdx.x * blockDim.x + threadIdx.x;
    if (idx < N)  g_rmax[idx] = (int)0x80000000;
    if (idx < NT) g_cmax[idx] = (int)0x80000000;
}

// ---------------------------------------------------------------------------
// K1: 128x128x16 tiled SGEMM, 256 threads, 8x8 microtile per thread.
// Epilogue: scale by 10, store S, reduce row/col maxes, atomicMax to globals.
__global__ __launch_bounds__(256, 2)
void gemm_kernel(const float* __restrict__ A, const float* __restrict__ B) {
    __shared__ float As[BK][BM + 4];
    __shared__ float Bs[BK][BN + 4];
    __shared__ float red[16][BM];   // reduction buffer (8 KB)

    const int tid = threadIdx.x;
    const int tx  = tid & 15;
    const int ty  = tid >> 4;
    const int bm  = blockIdx.y;
    const int bn  = blockIdx.x;

    const float* Ab = A + (size_t)bm * BM * D;
    const float* Bb = B + (size_t)bn * BN * D;

    float acc[8][8];
    #pragma unroll
    for (int r = 0; r < 8; r++)
        #pragma unroll
        for (int c = 0; c < 8; c++) acc[r][c] = 0.f;

    for (int k0 = 0; k0 < D; k0 += BK) {
        #pragma unroll
        for (int i = 0; i < 2; i++) {
            int idx = i * 256 + tid;
            int row = idx >> 2;
            int kq  = (idx & 3) << 2;
            float4 va = *reinterpret_cast<const float4*>(Ab + row * D + k0 + kq);
            As[kq + 0][row] = va.x; As[kq + 1][row] = va.y;
            As[kq + 2][row] = va.z; As[kq + 3][row] = va.w;
            float4 vb = *reinterpret_cast<const float4*>(Bb + row * D + k0 + kq);
            Bs[kq + 0][row] = vb.x; Bs[kq + 1][row] = vb.y;
            Bs[kq + 2][row] = vb.z; Bs[kq + 3][row] = vb.w;
        }
        __syncthreads();
        #pragma unroll
        for (int k = 0; k < BK; k++) {
            float a[8], b[8];
            *reinterpret_cast<float4*>(&a[0]) = *reinterpret_cast<const float4*>(&As[k][ty * 8]);
            *reinterpret_cast<float4*>(&a[4]) = *reinterpret_cast<const float4*>(&As[k][ty * 8 + 4]);
            *reinterpret_cast<float4*>(&b[0]) = *reinterpret_cast<const float4*>(&Bs[k][tx * 4]);
            *reinterpret_cast<float4*>(&b[4]) = *reinterpret_cast<const float4*>(&Bs[k][64 + tx * 4]);
            #pragma unroll
            for (int r = 0; r < 8; r++)
                #pragma unroll
                for (int c = 0; c < 8; c++)
                    acc[r][c] = fmaf(a[r], b[c], acc[r][c]);
        }
        __syncthreads();
    }

    // Epilogue: scale, per-thread maxes, store
    float rmx[8], cmx[8];
    #pragma unroll
    for (int r = 0; r < 8; r++) rmx[r] = -FLT_MAX;
    #pragma unroll
    for (int c = 0; c < 8; c++) cmx[c] = -FLT_MAX;

    #pragma unroll
    for (int r = 0; r < 8; r++) {
        #pragma unroll
        for (int c = 0; c < 8; c++) {
            float x = acc[r][c] * SCALE;
            acc[r][c] = x;
            rmx[r] = fmaxf(rmx[r], x);
            cmx[c] = fmaxf(cmx[c], x);
        }
        size_t gr = (size_t)(bm * BM + ty * 8 + r) * NT + (size_t)bn * BN;
        float4 o0 = make_float4(acc[r][0], acc[r][1], acc[r][2], acc[r][3]);
        float4 o1 = make_float4(acc[r][4], acc[r][5], acc[r][6], acc[r][7]);
        *reinterpret_cast<float4*>(&g_S[gr + tx * 4])      = o0;
        *reinterpret_cast<float4*>(&g_S[gr + 64 + tx * 4]) = o1;
    }

    // row-max reduce across the 16 threads sharing each row
    #pragma unroll
    for (int r = 0; r < 8; r++) red[tx][ty * 8 + r] = rmx[r];
    __syncthreads();
    if (tid < BM) {
        float m = red[0][tid];
        #pragma unroll
        for (int j = 1; j < 16; j++) m = fmaxf(m, red[j][tid]);
        atomicMax(&g_rmax[bm * BM + tid], enc_f(m));
    }
    __syncthreads();
    // col-max reduce across the 16 threads sharing each column
    #pragma unroll
    for (int c = 0; c < 8; c++) {
        int cl = (c < 4) ? (tx * 4 + c) : (64 + tx * 4 + (c - 4));
        red[ty][cl] = cmx[c];
    }
    __syncthreads();
    if (tid < BN) {
        float m = red[0][tid];
        #pragma unroll
        for (int j = 1; j < 16; j++) m = fmaxf(m, red[j][tid]);
        atomicMax(&g_cmax[bn * BN + tid], enc_f(m));
    }
}

// ---------------------------------------------------------------------------
// K2: column partial sumexp over 128-row tiles (coalesced, exp mostly skipped)
__global__ __launch_bounds__(256)
void colsum_kernel() {
    int col = blockIdx.x * 256 + threadIdx.x;
    int r0  = blockIdx.y * BM;
    float cm  = dec_f(g_cmax[col]);
    float thr = cm - LSE_CUT;
    float s = 0.f;
    #pragma unroll 8
    for (int r = 0; r < BM; r++) {
        float x = g_S[(size_t)(r0 + r) * NT + col];
        if (x > thr) s += expf(x - cm);
    }
    g_cpart[blockIdx.y][col] = s;
}

// ---------------------------------------------------------------------------
// K3: one block per row. Ranks (consistent values from stored S), row sumexp,
// LSE combine, per-row metrics.
__global__ __launch_bounds__(256)
void row_kernel() {
    const int i   = blockIdx.x;
    const int tid = threadIdx.x;
    const float* __restrict__ row = g_S + (size_t)i * NT;
    const int cbase = i * T;

    float p[T];
    #pragma unroll
    for (int t = 0; t < T; t++) p[t] = row[cbase + t];

    float rm  = dec_f(g_rmax[i]);
    float thr = rm - LSE_CUT;

    int cnt[T] = {0, 0, 0, 0};
    float s = 0.f;
    for (int j = tid; j < NT; j += 256) {
        float x = row[j];
        #pragma unroll
        for (int t = 0; t < T; t++)
            cnt[t] += (x > p[t]) || (x == p[t] && j < cbase + t);
        if (x > thr) s += expf(x - rm);
    }

    __shared__ int   scnt[T][256];
    __shared__ float ssum[256];
    #pragma unroll
    for (int t = 0; t < T; t++) scnt[t][tid] = cnt[t];
    ssum[tid] = s;
    __syncthreads();
    for (int off = 128; off > 0; off >>= 1) {
        if (tid < off) {
            #pragma unroll
            for (int t = 0; t < T; t++) scnt[t][tid] += scnt[t][tid + off];
            ssum[tid] += ssum[tid + off];
        }
        __syncthreads();
    }

    if (tid == 0) {
        float rsum = ssum[0];
        // nominator = LSE of the 4 positive scores
        float pm = fmaxf(fmaxf(p[0], p[1]), fmaxf(p[2], p[3]));
        float nom = pm + logf(expf(p[0] - pm) + expf(p[1] - pm) +
                              expf(p[2] - pm) + expf(p[3] - pm));
        // denominator = LSE over row entries + column entries of the 4 positives
        float cmv[T];
        float M = rm;
        #pragma unroll
        for (int t = 0; t < T; t++) {
            cmv[t] = dec_f(g_cmax[cbase + t]);
            M = fmaxf(M, cmv[t]);
        }
        float tot = rsum * expf(rm - M);
        #pragma unroll
        for (int t = 0; t < T; t++) {
            float cs = 0.f;
            for (int pth = 0; pth < RTILES; pth++) cs += g_cpart[pth][cbase + t];
            tot += cs * expf(cmv[t] - M);
        }
        float denom = M + logf(tot);

        float r1 = 0.f, r5 = 0.f, r10 = 0.f, ar = 0.f;
        #pragma unroll
        for (int t = 0; t < T; t++) {
            int rk = scnt[t][0];     // position in descending stable order
            r1  += (rk < 1);
            r5  += (rk < 5);
            r10 += (rk < 10);
            ar  += (float)rk;
        }
        g_rowout[i][0] = denom - nom;
        g_rowout[i][1] = r1  * 0.25f;
        g_rowout[i][2] = r5  * 0.25f;
        g_rowout[i][3] = r10 * 0.25f;
        g_rowout[i][4] = ar  * 0.25f;
    }
}

// ---------------------------------------------------------------------------
// K4: deterministic final reduction -> 5 means
__global__ __launch_bounds__(256)
void final_kernel(float* __restrict__ out) {
    __shared__ double sacc[5][256];
    int tid = threadIdx.x;
    double a[5] = {0, 0, 0, 0, 0};
    for (int i = tid; i < N; i += 256) {
        #pragma unroll
        for (int q = 0; q < 5; q++) a[q] += (double)g_rowout[i][q];
    }
    #pragma unroll
    for (int q = 0; q < 5; q++) sacc[q][tid] = a[q];
    __syncthreads();
    for (int off = 128; off > 0; off >>= 1) {
        if (tid < off) {
            #pragma unroll
            for (int q = 0; q < 5; q++) sacc[q][tid] += sacc[q][tid + off];
        }
        __syncthreads();
    }
    if (tid == 0) {
        #pragma unroll
        for (int q = 0; q < 5; q++) out[q] = (float)(sacc[q][0] / (double)N);
    }
}

// ---------------------------------------------------------------------------
extern "C" void kernel_launch(void* const* d_in, const int* in_sizes, int n_in,
                              void* d_out, int out_size) {
    const float* v = (const float*)d_in[0];   // [4096, 256]
    const float* t = (const float*)d_in[1];   // [16384, 256]
    (void)in_sizes; (void)n_in; (void)out_size;

    init_kernel<<<(NT + 255) / 256, 256>>>();
    gemm_kernel<<<dim3(NT / BN, N / BM), 256>>>(v, t);
    colsum_kernel<<<dim3(NT / 256, N / BM), 256>>>();
    row_kernel<<<N, 256>>>();
    final_kernel<<<1, 256>>>((float*)d_out);
}